// round 8
// baseline (speedup 1.0000x reference)
#include <cuda_runtime.h>

#define NB   8
#define NC   6
#define HH   512
#define WW   512
#define HW   (HH * WW)           // 262144
#define NPIX (NB * HW)           // 2097152

#define ETH  16                  // edge strip height (full 512-wide rows)
#define SS   528                 // smem column stride; image col c stored at c+8

#define LOSS_BLOCKS ((NPIX / 4) / 256)   // 2048
#define NSLOT 32                          // distributed accumulator slots

#define L2E  1.4426950408889634f  // log2(e)
#define LN2  0.6931471805599453   // ln(2), applied once in finalize

// Distributed accumulators: 32 slots per variable, 256B stride so each slot
// lands on a different L2 slice -> atomic ops pipeline instead of serializing
// on one address. Statically zero; last block resets them each launch.
__device__ __align__(256) double       gA[NSLOT][32];  // use [i][0]
__device__ __align__(256) double       gB[NSLOT][32];
__device__ __align__(256) double       gC[NSLOT][32];
__device__ __align__(256) unsigned int gN[NSLOT][64];
__device__ unsigned int g_done = 0u;
__device__ __align__(16) unsigned char g_pack[NPIX];  // label | (edge << 3)

__device__ __forceinline__ float ex2f(float v) {
    float r; asm("ex2.approx.f32 %0, %1;" : "=f"(r) : "f"(v)); return r;
}
__device__ __forceinline__ float lg2f(float v) {
    float r; asm("lg2.approx.f32 %0, %1;" : "=f"(r) : "f"(v)); return r;
}

// ---------------------------------------------------------------------------
// Kernel 1: full-width strip, exact integer 11x11 box sum, packed byte out.
// ---------------------------------------------------------------------------
__global__ void __launch_bounds__(512)
edge_pack_kernel(const int* __restrict__ target) {
    __shared__ unsigned char  t_s[(ETH + 10) * SS];   // 26*528 = 13728 B
    __shared__ unsigned short csum_s[ETH * SS];       // 16*528*2 = 16896 B

    const int tid = threadIdx.x;
    const int y0  = blockIdx.x * ETH;
    const int b   = blockIdx.y;
    const int* tb = target + b * HW;

    // Zero both arrays (guard columns / out-of-image rows must read as 0)
    {
        uint4* p1 = reinterpret_cast<uint4*>(t_s);      // 13728/16 = 858
        for (int i = tid; i < 858; i += 512) p1[i] = make_uint4(0, 0, 0, 0);
        uint4* p2 = reinterpret_cast<uint4*>(csum_s);   // 16896/16 = 1056
        for (int i = tid; i < 1056; i += 512) p2[i] = make_uint4(0, 0, 0, 0);
    }
    __syncthreads();

    // Phase 1: load rows y0-5 .. y0+20 (clamped) as bytes; col c at pos c+8
#pragma unroll
    for (int r = 0; r < ETH + 10; r++) {
        const int gy = y0 + r - 5;
        if (gy >= 0 && gy < HH)
            t_s[r * SS + tid + 8] = (unsigned char)tb[gy * WW + tid];
    }
    __syncthreads();

    // Phase 2: vertical sliding 11-sums; one column per thread
    {
        const int pos = tid + 8;
        int s = 0;
#pragma unroll
        for (int i = 0; i < 11; i++) s += t_s[i * SS + pos];
        csum_s[pos] = (unsigned short)s;
#pragma unroll
        for (int r = 1; r < ETH; r++) {
            s += (int)t_s[(r + 10) * SS + pos] - (int)t_s[(r - 1) * SS + pos];
            csum_s[r * SS + pos] = (unsigned short)s;
        }
    }
    __syncthreads();

    // Phase 3: 16 rows x 32 lanes; each thread 16 consecutive pixels.
    {
        const int r  = tid >> 5;          // 0..15
        const int xs = (tid & 31) * 16;   // 0,16,...,496

        unsigned int w[16];
        {
            const uint4* src = reinterpret_cast<const uint4*>(&csum_s[r * SS + xs]);
            uint4 u0 = src[0], u1 = src[1], u2 = src[2], u3 = src[3];
            w[0]=u0.x; w[1]=u0.y; w[2]=u0.z; w[3]=u0.w;
            w[4]=u1.x; w[5]=u1.y; w[6]=u1.z; w[7]=u1.w;
            w[8]=u2.x; w[9]=u2.y; w[10]=u2.z; w[11]=u2.w;
            w[12]=u3.x; w[13]=u3.y; w[14]=u3.z; w[15]=u3.w;
        }
#define CS(L) ((int)((w[(L) >> 1] >> (((L) & 1) * 16)) & 0xFFFFu))

        unsigned int lw[4];
        {
            const uint2* lp0 = reinterpret_cast<const uint2*>(
                &t_s[(r + 5) * SS + xs + 8]);
            uint2 l0 = lp0[0], l1 = lp0[1];
            lw[0] = l0.x; lw[1] = l0.y; lw[2] = l1.x; lw[3] = l1.y;
        }

        int s = 0;
#pragma unroll
        for (int d = 0; d < 11; d++) s += CS(3 + d);

        unsigned int out[4] = {0u, 0u, 0u, 0u};
#pragma unroll
        for (int k = 0; k < 16; k++) {
            if (k) s += CS(k + 13) - CS(k + 2);
            const int lab = (int)((lw[k >> 2] >> (8 * (k & 3))) & 0xFFu);
            const unsigned int e = (121 * lab != s) ? 1u : 0u;
            out[k >> 2] |= ((unsigned int)lab | (e << 3)) << (8 * (k & 3));
        }
#undef CS
        *reinterpret_cast<uint4*>(&g_pack[b * HW + (y0 + r) * WW + xs]) =
            make_uint4(out[0], out[1], out[2], out[3]);
    }
}

// ---------------------------------------------------------------------------
// Kernel 2: streaming fused log-softmax loss, 4 px/thread, register LDGs,
// channel loop (no register arrays -> no spills). Atomics distributed over
// 32 L2 slots to kill single-address RED serialization.
// ---------------------------------------------------------------------------
__global__ void __launch_bounds__(256)
loss_kernel(const float* __restrict__ x, float* __restrict__ out) {
    const int tid = threadIdx.x;
    const int t4 = blockIdx.x * blockDim.x + tid;     // 0 .. NPIX/4-1
    const int p0 = t4 * 4;
    const int b  = p0 >> 18;         // / HW
    const int hw = p0 & (HW - 1);

    const float4* xb = reinterpret_cast<const float4*>(
        x + (size_t)b * NC * HW + hw);

    const unsigned int pk = *reinterpret_cast<const unsigned int*>(g_pack + p0);
    const int lab0 = (int)( pk        & 7u), e0 = (int)((pk >> 3)  & 1u);
    const int lab1 = (int)((pk >> 8)  & 7u), e1 = (int)((pk >> 11) & 1u);
    const int lab2 = (int)((pk >> 16) & 7u), e2 = (int)((pk >> 19) & 1u);
    const int lab3 = (int)((pk >> 24) & 7u), e3 = (int)((pk >> 27) & 1u);

    float es0 = 0.f, es1 = 0.f, es2 = 0.f, es3 = 0.f;   // sum 2^(x*log2e)
    float T0  = 0.f, T1  = 0.f, T2  = 0.f, T3  = 0.f;   // sum x
    float xl0 = 0.f, xl1 = 0.f, xl2 = 0.f, xl3 = 0.f;   // x at label

#pragma unroll
    for (int c = 0; c < NC; c++) {
        const float4 f = xb[c * (HW / 4)];
        es0 += ex2f(f.x * L2E);
        es1 += ex2f(f.y * L2E);
        es2 += ex2f(f.z * L2E);
        es3 += ex2f(f.w * L2E);
        T0 += f.x;  T1 += f.y;  T2 += f.z;  T3 += f.w;
        xl0 = (lab0 == c) ? f.x : xl0;
        xl1 = (lab1 == c) ? f.y : xl1;
        xl2 = (lab2 == c) ? f.z : xl2;
        xl3 = (lab3 == c) ? f.w : xl3;
    }

    // Per-pixel epilogue in log2 domain
    const float l0 = lg2f(es0), l1 = lg2f(es1), l2 = lg2f(es2), l3 = lg2f(es3);
    const float lp0 = fmaf(xl0, L2E, -l0);
    const float lp1 = fmaf(xl1, L2E, -l1);
    const float lp2 = fmaf(xl2, L2E, -l2);
    const float lp3 = fmaf(xl3, L2E, -l3);
    const float S0 = fmaf(l0, -6.0f, T0 * L2E);
    const float S1 = fmaf(l1, -6.0f, T1 * L2E);
    const float S2 = fmaf(l2, -6.0f, T2 * L2E);
    const float S3 = fmaf(l3, -6.0f, T3 * L2E);
    const float f0 = (float)e0, f1 = (float)e1, f2 = (float)e2, f3 = (float)e3;

    float accA = (lp0 + lp1) + (lp2 + lp3);
    float accB = fmaf(f0, S0,  fmaf(f1, S1,  fmaf(f2, S2,  f3 * S3)));
    float accC = fmaf(f0, lp0, fmaf(f1, lp1, fmaf(f2, lp2, f3 * lp3)));
    int   accN = (e0 + e1) + (e2 + e3);

    // Block reduction, then 4 atomics to this block's slot
#pragma unroll
    for (int off = 16; off; off >>= 1) {
        accA += __shfl_down_sync(0xffffffffu, accA, off);
        accB += __shfl_down_sync(0xffffffffu, accB, off);
        accC += __shfl_down_sync(0xffffffffu, accC, off);
        accN += __shfl_down_sync(0xffffffffu, accN, off);
    }
    __shared__ float red[3 * 8];
    __shared__ int   redn[8];
    __shared__ bool  is_last;
    const int lane = tid & 31, w = tid >> 5;
    if (lane == 0) { red[w] = accA; red[8 + w] = accB; red[16 + w] = accC; redn[w] = accN; }
    __syncthreads();
    if (tid < 8) {
        float a = red[tid], bb = red[8 + tid], c = red[16 + tid];
        int   n = redn[tid];
#pragma unroll
        for (int off = 4; off; off >>= 1) {
            a  += __shfl_down_sync(0x000000ffu, a, off);
            bb += __shfl_down_sync(0x000000ffu, bb, off);
            c  += __shfl_down_sync(0x000000ffu, c, off);
            n  += __shfl_down_sync(0x000000ffu, n, off);
        }
        if (tid == 0) {
            const int slot = blockIdx.x & (NSLOT - 1);
            atomicAdd(&gA[slot][0], (double)a);
            atomicAdd(&gB[slot][0], (double)bb);
            atomicAdd(&gC[slot][0], (double)c);
            atomicAdd(&gN[slot][0], (unsigned int)n);
        }
    }

    // Last-block finalize: gather slots, scalar math, output, reset
    if (tid == 0) {
        __threadfence();
        const unsigned int prev = atomicAdd(&g_done, 1u);
        is_last = (prev == (unsigned int)(LOSS_BLOCKS - 1));
    }
    __syncthreads();
    if (is_last && tid == 0) {
        __threadfence();
        double A = 0.0, B = 0.0, C = 0.0;
        unsigned int cnt = 0u;
#pragma unroll
        for (int i = 0; i < NSLOT; i++) {
            A += *(volatile double*)&gA[i][0];
            B += *(volatile double*)&gB[i][0];
            C += *(volatile double*)&gC[i][0];
            cnt += *(volatile unsigned int*)&gN[i][0];
        }

        const double s  = fmin((double)cnt / (double)NPIX, 0.2);
        const double cl = 1.0 - 2.0 * s + s / 6.0;
        const double total = LN2 * (A + s * B + (cl - 1.0) * C);
        out[0] = (float)(-(total / (double)NPIX));

#pragma unroll
        for (int i = 0; i < NSLOT; i++) {
            gA[i][0] = 0.0; gB[i][0] = 0.0; gC[i][0] = 0.0; gN[i][0] = 0u;
        }
        g_done = 0u;
    }
}

extern "C" void kernel_launch(void* const* d_in, const int* in_sizes, int n_in,
                              void* d_out, int out_size) {
    const float* x      = (const float*)d_in[0];
    const int*   target = (const int*)d_in[1];
    float*       out    = (float*)d_out;

    dim3 eg(HH / ETH, NB);            // (32, 8) = 256 blocks x 512 threads
    edge_pack_kernel<<<eg, 512>>>(target);

    loss_kernel<<<LOSS_BLOCKS, 256>>>(x, out);
}

// round 9
// speedup vs baseline: 1.0555x; 1.0555x over previous
#include <cuda_runtime.h>

#define NB   8
#define NC   6
#define HH   512
#define WW   512
#define HW   (HH * WW)           // 262144
#define NPIX (NB * HW)           // 2097152

#define ETH  16                  // edge strip height (full 512-wide rows)
#define SS   528                 // smem column stride; image col c stored at c+8

#define LOSS_BLOCKS ((NPIX / 2) / 256)   // 4096

#define L2E  1.4426950408889634f  // log2(e)
#define LN2  0.6931471805599453   // ln(2), applied once in finalize

// Scratch: per-block partials {A, B, C, N}. Fully rewritten every launch by
// loss_kernel before reduce_kernel reads it -> no persistent state, no resets,
// no atomics anywhere.
__device__ __align__(16) float4 g_part[LOSS_BLOCKS];
__device__ __align__(16) unsigned char g_pack[NPIX];  // label | (edge << 3)

__device__ __forceinline__ float ex2f(float v) {
    float r; asm("ex2.approx.f32 %0, %1;" : "=f"(r) : "f"(v)); return r;
}
__device__ __forceinline__ float lg2f(float v) {
    float r; asm("lg2.approx.f32 %0, %1;" : "=f"(r) : "f"(v)); return r;
}

// ---------------------------------------------------------------------------
// Kernel 1: full-width strip, exact integer 11x11 box sum, packed byte out.
// ---------------------------------------------------------------------------
__global__ void __launch_bounds__(512)
edge_pack_kernel(const int* __restrict__ target) {
    __shared__ unsigned char  t_s[(ETH + 10) * SS];   // 26*528 = 13728 B
    __shared__ unsigned short csum_s[ETH * SS];       // 16*528*2 = 16896 B

    const int tid = threadIdx.x;
    const int y0  = blockIdx.x * ETH;
    const int b   = blockIdx.y;
    const int* tb = target + b * HW;

    // Zero both arrays (guard columns / out-of-image rows must read as 0)
    {
        uint4* p1 = reinterpret_cast<uint4*>(t_s);      // 13728/16 = 858
        for (int i = tid; i < 858; i += 512) p1[i] = make_uint4(0, 0, 0, 0);
        uint4* p2 = reinterpret_cast<uint4*>(csum_s);   // 16896/16 = 1056
        for (int i = tid; i < 1056; i += 512) p2[i] = make_uint4(0, 0, 0, 0);
    }
    __syncthreads();

    // Phase 1: load rows y0-5 .. y0+20 (clamped) as bytes; col c at pos c+8
#pragma unroll
    for (int r = 0; r < ETH + 10; r++) {
        const int gy = y0 + r - 5;
        if (gy >= 0 && gy < HH)
            t_s[r * SS + tid + 8] = (unsigned char)tb[gy * WW + tid];
    }
    __syncthreads();

    // Phase 2: vertical sliding 11-sums; one column per thread
    {
        const int pos = tid + 8;
        int s = 0;
#pragma unroll
        for (int i = 0; i < 11; i++) s += t_s[i * SS + pos];
        csum_s[pos] = (unsigned short)s;
#pragma unroll
        for (int r = 1; r < ETH; r++) {
            s += (int)t_s[(r + 10) * SS + pos] - (int)t_s[(r - 1) * SS + pos];
            csum_s[r * SS + pos] = (unsigned short)s;
        }
    }
    __syncthreads();

    // Phase 3: 16 rows x 32 lanes; each thread 16 consecutive pixels.
    {
        const int r  = tid >> 5;          // 0..15
        const int xs = (tid & 31) * 16;   // 0,16,...,496

        unsigned int w[16];
        {
            const uint4* src = reinterpret_cast<const uint4*>(&csum_s[r * SS + xs]);
            uint4 u0 = src[0], u1 = src[1], u2 = src[2], u3 = src[3];
            w[0]=u0.x; w[1]=u0.y; w[2]=u0.z; w[3]=u0.w;
            w[4]=u1.x; w[5]=u1.y; w[6]=u1.z; w[7]=u1.w;
            w[8]=u2.x; w[9]=u2.y; w[10]=u2.z; w[11]=u2.w;
            w[12]=u3.x; w[13]=u3.y; w[14]=u3.z; w[15]=u3.w;
        }
#define CS(L) ((int)((w[(L) >> 1] >> (((L) & 1) * 16)) & 0xFFFFu))

        unsigned int lw[4];
        {
            const uint2* lp0 = reinterpret_cast<const uint2*>(
                &t_s[(r + 5) * SS + xs + 8]);
            uint2 l0 = lp0[0], l1 = lp0[1];
            lw[0] = l0.x; lw[1] = l0.y; lw[2] = l1.x; lw[3] = l1.y;
        }

        int s = 0;
#pragma unroll
        for (int d = 0; d < 11; d++) s += CS(3 + d);

        unsigned int out[4] = {0u, 0u, 0u, 0u};
#pragma unroll
        for (int k = 0; k < 16; k++) {
            if (k) s += CS(k + 13) - CS(k + 2);
            const int lab = (int)((lw[k >> 2] >> (8 * (k & 3))) & 0xFFu);
            const unsigned int e = (121 * lab != s) ? 1u : 0u;
            out[k >> 2] |= ((unsigned int)lab | (e << 3)) << (8 * (k & 3));
        }
#undef CS
        *reinterpret_cast<uint4*>(&g_pack[b * HW + (y0 + r) * WW + xs]) =
            make_uint4(out[0], out[1], out[2], out[3]);
    }
}

// ---------------------------------------------------------------------------
// Kernel 2: streaming fused log-softmax loss, 2 px/thread (max warp count),
// channel loop (no register arrays), log2 domain. NO atomics: one STG.128 of
// per-block partials {A,B,C,N}.
// ---------------------------------------------------------------------------
__global__ void __launch_bounds__(256)
loss_kernel(const float* __restrict__ x) {
    const int tid = threadIdx.x;
    const int t  = blockIdx.x * blockDim.x + tid;   // 0 .. NPIX/2-1
    const int p0 = t * 2;
    const int b  = p0 >> 18;         // / HW
    const int hw = p0 & (HW - 1);

    const float* xb = x + (size_t)b * NC * HW + hw;

    const unsigned int pk =
        *reinterpret_cast<const unsigned short*>(g_pack + p0);
    const int lab0 = (int)( pk       & 7u), e0 = (int)((pk >> 3)  & 1u);
    const int lab1 = (int)((pk >> 8) & 7u), e1 = (int)((pk >> 11) & 1u);

    float es0 = 0.f, es1 = 0.f;     // sum 2^(x*log2e)
    float T0  = 0.f, T1  = 0.f;     // sum x
    float xl0 = 0.f, xl1 = 0.f;     // x at label

#pragma unroll
    for (int c = 0; c < NC; c++) {
        const float2 f = *reinterpret_cast<const float2*>(xb + c * HW);
        es0 += ex2f(f.x * L2E);
        es1 += ex2f(f.y * L2E);
        T0 += f.x;  T1 += f.y;
        xl0 = (lab0 == c) ? f.x : xl0;
        xl1 = (lab1 == c) ? f.y : xl1;
    }

    // Per-pixel epilogue in log2 domain
    const float l0 = lg2f(es0), l1 = lg2f(es1);
    const float lp0 = fmaf(xl0, L2E, -l0);
    const float lp1 = fmaf(xl1, L2E, -l1);
    const float S0 = fmaf(l0, -6.0f, T0 * L2E);
    const float S1 = fmaf(l1, -6.0f, T1 * L2E);
    const float f0 = (float)e0, f1 = (float)e1;

    float accA = lp0 + lp1;
    float accB = fmaf(f0, S0,  f1 * S1);
    float accC = fmaf(f0, lp0, f1 * lp1);
    int   accN = e0 + e1;

    // Block reduction -> one plain STG.128 (no atomics)
#pragma unroll
    for (int off = 16; off; off >>= 1) {
        accA += __shfl_down_sync(0xffffffffu, accA, off);
        accB += __shfl_down_sync(0xffffffffu, accB, off);
        accC += __shfl_down_sync(0xffffffffu, accC, off);
        accN += __shfl_down_sync(0xffffffffu, accN, off);
    }
    __shared__ float red[3 * 8];
    __shared__ int   redn[8];
    const int lane = tid & 31, w = tid >> 5;
    if (lane == 0) { red[w] = accA; red[8 + w] = accB; red[16 + w] = accC; redn[w] = accN; }
    __syncthreads();
    if (tid < 8) {
        float a = red[tid], bb = red[8 + tid], c = red[16 + tid];
        int   n = redn[tid];
#pragma unroll
        for (int off = 4; off; off >>= 1) {
            a  += __shfl_down_sync(0x000000ffu, a, off);
            bb += __shfl_down_sync(0x000000ffu, bb, off);
            c  += __shfl_down_sync(0x000000ffu, c, off);
            n  += __shfl_down_sync(0x000000ffu, n, off);
        }
        if (tid == 0)
            g_part[blockIdx.x] = make_float4(a, bb, c, (float)n);
    }
}

// ---------------------------------------------------------------------------
// Kernel 3: reduce 4096 partials (fixed order -> deterministic), finalize.
// ---------------------------------------------------------------------------
__global__ void __launch_bounds__(256)
reduce_kernel(float* __restrict__ out) {
    const int tid = threadIdx.x;

    double A = 0.0, B = 0.0, C = 0.0;
    float  N = 0.0f;
#pragma unroll
    for (int k = 0; k < LOSS_BLOCKS / 256; k++) {        // 16 iterations
        const float4 p = g_part[tid + k * 256];
        A += (double)p.x; B += (double)p.y; C += (double)p.z; N += p.w;
    }

    // Warp reduce (doubles shuffle as 2x b32 automatically)
#pragma unroll
    for (int off = 16; off; off >>= 1) {
        A += __shfl_down_sync(0xffffffffu, A, off);
        B += __shfl_down_sync(0xffffffffu, B, off);
        C += __shfl_down_sync(0xffffffffu, C, off);
        N += __shfl_down_sync(0xffffffffu, N, off);
    }
    __shared__ double rA[8], rB[8], rC[8];
    __shared__ float  rN[8];
    const int lane = tid & 31, w = tid >> 5;
    if (lane == 0) { rA[w] = A; rB[w] = B; rC[w] = C; rN[w] = N; }
    __syncthreads();
    if (tid == 0) {
        double sA = 0.0, sB = 0.0, sC = 0.0;
        float  sN = 0.0f;
#pragma unroll
        for (int i = 0; i < 8; i++) { sA += rA[i]; sB += rB[i]; sC += rC[i]; sN += rN[i]; }

        const double s  = fmin((double)sN / (double)NPIX, 0.2);
        const double cl = 1.0 - 2.0 * s + s / 6.0;
        const double total = LN2 * (sA + s * sB + (cl - 1.0) * sC);
        out[0] = (float)(-(total / (double)NPIX));
    }
}

extern "C" void kernel_launch(void* const* d_in, const int* in_sizes, int n_in,
                              void* d_out, int out_size) {
    const float* x      = (const float*)d_in[0];
    const int*   target = (const int*)d_in[1];
    float*       out    = (float*)d_out;

    dim3 eg(HH / ETH, NB);            // (32, 8) = 256 blocks x 512 threads
    edge_pack_kernel<<<eg, 512>>>(target);

    loss_kernel<<<LOSS_BLOCKS, 256>>>(x);

    reduce_kernel<<<1, 256>>>(out);
}

// round 10
// speedup vs baseline: 1.5422x; 1.4611x over previous
#include <cuda_runtime.h>

#define NB   8
#define NC   6
#define HH   512
#define WW   512
#define HW   (HH * WW)           // 262144
#define NPIX (NB * HW)           // 2097152

#define ETH  16                  // edge strip height (full 512-wide rows)
#define SS   528                 // smem column stride; image col c stored at c+8

#define LOSS_BLOCKS ((NPIX / 8) / 128)   // 2048

#define L2E  1.4426950408889634f  // log2(e)
#define LN2  0.6931471805599453   // ln(2), applied once in finalize

// Global accumulators (log2-domain sums). Statically zero; loss kernel's
// last block resets them so every graph replay starts from zero.
__device__ double       g_A = 0.0;   // sum lp2 over all pixels
__device__ double       g_B = 0.0;   // sum S2  over edge pixels
__device__ double       g_C = 0.0;   // sum lp2 over edge pixels
__device__ unsigned int g_count = 0u;
__device__ unsigned int g_done  = 0u;
__device__ __align__(16) unsigned char g_pack[NPIX];  // label | (edge << 3)

__device__ __forceinline__ float ex2f(float v) {
    float r; asm("ex2.approx.f32 %0, %1;" : "=f"(r) : "f"(v)); return r;
}
__device__ __forceinline__ float lg2f(float v) {
    float r; asm("lg2.approx.f32 %0, %1;" : "=f"(r) : "f"(v)); return r;
}
__device__ __forceinline__ unsigned long long pack2(float lo, float hi) {
    unsigned long long r;
    asm("mov.b64 %0, {%1, %2};" : "=l"(r) : "f"(lo), "f"(hi));
    return r;
}
__device__ __forceinline__ void unpack2(unsigned long long p, float& lo, float& hi) {
    asm("mov.b64 {%0, %1}, %2;" : "=f"(lo), "=f"(hi) : "l"(p));
}
__device__ __forceinline__ unsigned long long add2(unsigned long long a,
                                                   unsigned long long b) {
    unsigned long long r;
    asm("add.rn.f32x2 %0, %1, %2;" : "=l"(r) : "l"(a), "l"(b));
    return r;
}

// ---------------------------------------------------------------------------
// Kernel 1: full-width strip, exact integer 11x11 box sum, packed byte out.
// ---------------------------------------------------------------------------
__global__ void __launch_bounds__(512)
edge_pack_kernel(const int* __restrict__ target) {
    __shared__ unsigned char  t_s[(ETH + 10) * SS];   // 26*528 = 13728 B
    __shared__ unsigned short csum_s[ETH * SS];       // 16*528*2 = 16896 B

    const int tid = threadIdx.x;
    const int y0  = blockIdx.x * ETH;
    const int b   = blockIdx.y;
    const int* tb = target + b * HW;

    // Zero both arrays (guard columns / out-of-image rows must read as 0)
    {
        uint4* p1 = reinterpret_cast<uint4*>(t_s);      // 13728/16 = 858
        for (int i = tid; i < 858; i += 512) p1[i] = make_uint4(0, 0, 0, 0);
        uint4* p2 = reinterpret_cast<uint4*>(csum_s);   // 16896/16 = 1056
        for (int i = tid; i < 1056; i += 512) p2[i] = make_uint4(0, 0, 0, 0);
    }
    __syncthreads();

    // Phase 1: load rows y0-5 .. y0+20 (clamped) as bytes; col c at pos c+8
#pragma unroll
    for (int r = 0; r < ETH + 10; r++) {
        const int gy = y0 + r - 5;
        if (gy >= 0 && gy < HH)
            t_s[r * SS + tid + 8] = (unsigned char)tb[gy * WW + tid];
    }
    __syncthreads();

    // Phase 2: vertical sliding 11-sums; one column per thread
    {
        const int pos = tid + 8;
        int s = 0;
#pragma unroll
        for (int i = 0; i < 11; i++) s += t_s[i * SS + pos];
        csum_s[pos] = (unsigned short)s;
#pragma unroll
        for (int r = 1; r < ETH; r++) {
            s += (int)t_s[(r + 10) * SS + pos] - (int)t_s[(r - 1) * SS + pos];
            csum_s[r * SS + pos] = (unsigned short)s;
        }
    }
    __syncthreads();

    // Phase 3: 16 rows x 32 lanes; each thread 16 consecutive pixels.
    {
        const int r  = tid >> 5;          // 0..15
        const int xs = (tid & 31) * 16;   // 0,16,...,496

        unsigned int w[16];
        {
            const uint4* src = reinterpret_cast<const uint4*>(&csum_s[r * SS + xs]);
            uint4 u0 = src[0], u1 = src[1], u2 = src[2], u3 = src[3];
            w[0]=u0.x; w[1]=u0.y; w[2]=u0.z; w[3]=u0.w;
            w[4]=u1.x; w[5]=u1.y; w[6]=u1.z; w[7]=u1.w;
            w[8]=u2.x; w[9]=u2.y; w[10]=u2.z; w[11]=u2.w;
            w[12]=u3.x; w[13]=u3.y; w[14]=u3.z; w[15]=u3.w;
        }
#define CS(L) ((int)((w[(L) >> 1] >> (((L) & 1) * 16)) & 0xFFFFu))

        unsigned int lw[4];
        {
            const uint2* lp0 = reinterpret_cast<const uint2*>(
                &t_s[(r + 5) * SS + xs + 8]);
            uint2 l0 = lp0[0], l1 = lp0[1];
            lw[0] = l0.x; lw[1] = l0.y; lw[2] = l1.x; lw[3] = l1.y;
        }

        int s = 0;
#pragma unroll
        for (int d = 0; d < 11; d++) s += CS(3 + d);

        unsigned int out[4] = {0u, 0u, 0u, 0u};
#pragma unroll
        for (int k = 0; k < 16; k++) {
            if (k) s += CS(k + 13) - CS(k + 2);
            const int lab = (int)((lw[k >> 2] >> (8 * (k & 3))) & 0xFFu);
            const unsigned int e = (121 * lab != s) ? 1u : 0u;
            out[k >> 2] |= ((unsigned int)lab | (e << 3)) << (8 * (k & 3));
        }
#undef CS
        *reinterpret_cast<uint4*>(&g_pack[b * HW + (y0 + r) * WW + xs]) =
            make_uint4(out[0], out[1], out[2], out[3]);
    }
}

// ---------------------------------------------------------------------------
// Kernel 2: streaming fused log-softmax loss, 8 px/thread, 128-thread blocks
// (grid 2048). Channel loop, no register arrays (no spills). Packed f32x2
// T-accumulators; REDUX for edge count. Log2 domain.
// ---------------------------------------------------------------------------
__global__ void __launch_bounds__(128)
loss_kernel(const float* __restrict__ x, float* __restrict__ out) {
    const int tid = threadIdx.x;
    const int t  = blockIdx.x * blockDim.x + tid;   // 0 .. NPIX/8-1
    const int p0 = t * 8;
    const int b  = p0 >> 18;         // / HW
    const int hw = p0 & (HW - 1);

    const float4* xb = reinterpret_cast<const float4*>(
        x + (size_t)b * NC * HW + hw);

    const uint2 pkv = *reinterpret_cast<const uint2*>(g_pack + p0);
    const int lab0 = (int)( pkv.x        & 7u), e0 = (int)((pkv.x >> 3)  & 1u);
    const int lab1 = (int)((pkv.x >> 8)  & 7u), e1 = (int)((pkv.x >> 11) & 1u);
    const int lab2 = (int)((pkv.x >> 16) & 7u), e2 = (int)((pkv.x >> 19) & 1u);
    const int lab3 = (int)((pkv.x >> 24) & 7u), e3 = (int)((pkv.x >> 27) & 1u);
    const int lab4 = (int)( pkv.y        & 7u), e4 = (int)((pkv.y >> 3)  & 1u);
    const int lab5 = (int)((pkv.y >> 8)  & 7u), e5 = (int)((pkv.y >> 11) & 1u);
    const int lab6 = (int)((pkv.y >> 16) & 7u), e6 = (int)((pkv.y >> 19) & 1u);
    const int lab7 = (int)((pkv.y >> 24) & 7u), e7 = (int)((pkv.y >> 27) & 1u);

    float es0 = 0.f, es1 = 0.f, es2 = 0.f, es3 = 0.f;
    float es4 = 0.f, es5 = 0.f, es6 = 0.f, es7 = 0.f;
    unsigned long long T01 = 0ull, T23 = 0ull, T45 = 0ull, T67 = 0ull;
    float xl0 = 0.f, xl1 = 0.f, xl2 = 0.f, xl3 = 0.f;
    float xl4 = 0.f, xl5 = 0.f, xl6 = 0.f, xl7 = 0.f;

#pragma unroll
    for (int c = 0; c < NC; c++) {
        const float4 fa = xb[c * (HW / 4)];
        const float4 fb = xb[c * (HW / 4) + 1];
        es0 += ex2f(fa.x * L2E);  es1 += ex2f(fa.y * L2E);
        es2 += ex2f(fa.z * L2E);  es3 += ex2f(fa.w * L2E);
        es4 += ex2f(fb.x * L2E);  es5 += ex2f(fb.y * L2E);
        es6 += ex2f(fb.z * L2E);  es7 += ex2f(fb.w * L2E);
        T01 = add2(T01, pack2(fa.x, fa.y));
        T23 = add2(T23, pack2(fa.z, fa.w));
        T45 = add2(T45, pack2(fb.x, fb.y));
        T67 = add2(T67, pack2(fb.z, fb.w));
        xl0 = (lab0 == c) ? fa.x : xl0;
        xl1 = (lab1 == c) ? fa.y : xl1;
        xl2 = (lab2 == c) ? fa.z : xl2;
        xl3 = (lab3 == c) ? fa.w : xl3;
        xl4 = (lab4 == c) ? fb.x : xl4;
        xl5 = (lab5 == c) ? fb.y : xl5;
        xl6 = (lab6 == c) ? fb.z : xl6;
        xl7 = (lab7 == c) ? fb.w : xl7;
    }

    // Per-pixel epilogue in log2 domain
    float T0, T1, T2, T3, T4, T5, T6, T7;
    unpack2(T01, T0, T1); unpack2(T23, T2, T3);
    unpack2(T45, T4, T5); unpack2(T67, T6, T7);

    const float l0 = lg2f(es0), l1 = lg2f(es1), l2 = lg2f(es2), l3 = lg2f(es3);
    const float l4 = lg2f(es4), l5 = lg2f(es5), l6 = lg2f(es6), l7 = lg2f(es7);

    const float lp0 = fmaf(xl0, L2E, -l0), lp1 = fmaf(xl1, L2E, -l1);
    const float lp2 = fmaf(xl2, L2E, -l2), lp3 = fmaf(xl3, L2E, -l3);
    const float lp4 = fmaf(xl4, L2E, -l4), lp5 = fmaf(xl5, L2E, -l5);
    const float lp6 = fmaf(xl6, L2E, -l6), lp7 = fmaf(xl7, L2E, -l7);

    const float S0 = fmaf(l0, -6.0f, T0 * L2E), S1 = fmaf(l1, -6.0f, T1 * L2E);
    const float S2 = fmaf(l2, -6.0f, T2 * L2E), S3 = fmaf(l3, -6.0f, T3 * L2E);
    const float S4 = fmaf(l4, -6.0f, T4 * L2E), S5 = fmaf(l5, -6.0f, T5 * L2E);
    const float S6 = fmaf(l6, -6.0f, T6 * L2E), S7 = fmaf(l7, -6.0f, T7 * L2E);

    const float f0 = (float)e0, f1 = (float)e1, f2 = (float)e2, f3 = (float)e3;
    const float f4 = (float)e4, f5 = (float)e5, f6 = (float)e6, f7 = (float)e7;

    float accA = ((lp0 + lp1) + (lp2 + lp3)) + ((lp4 + lp5) + (lp6 + lp7));
    float accB = fmaf(f0, S0, fmaf(f1, S1, fmaf(f2, S2, f3 * S3)))
               + fmaf(f4, S4, fmaf(f5, S5, fmaf(f6, S6, f7 * S7)));
    float accC = fmaf(f0, lp0, fmaf(f1, lp1, fmaf(f2, lp2, f3 * lp3)))
               + fmaf(f4, lp4, fmaf(f5, lp5, fmaf(f6, lp6, f7 * lp7)));
    int   accN = ((e0 + e1) + (e2 + e3)) + ((e4 + e5) + (e6 + e7));

    // Warp reduction: REDUX for the int count, shuffles for the 3 floats
    accN = __reduce_add_sync(0xffffffffu, accN);
#pragma unroll
    for (int off = 16; off; off >>= 1) {
        accA += __shfl_down_sync(0xffffffffu, accA, off);
        accB += __shfl_down_sync(0xffffffffu, accB, off);
        accC += __shfl_down_sync(0xffffffffu, accC, off);
    }
    __shared__ float red[3 * 4];
    __shared__ int   redn[4];
    __shared__ bool  is_last;
    const int lane = tid & 31, w = tid >> 5;   // 4 warps
    if (lane == 0) { red[w] = accA; red[4 + w] = accB; red[8 + w] = accC; redn[w] = accN; }
    __syncthreads();
    if (tid < 4) {
        float a = red[tid], bb = red[4 + tid], c = red[8 + tid];
        int   n = redn[tid];
#pragma unroll
        for (int off = 2; off; off >>= 1) {
            a  += __shfl_down_sync(0x0000000fu, a, off);
            bb += __shfl_down_sync(0x0000000fu, bb, off);
            c  += __shfl_down_sync(0x0000000fu, c, off);
            n  += __shfl_down_sync(0x0000000fu, n, off);
        }
        if (tid == 0) {
            atomicAdd(&g_A, (double)a);
            atomicAdd(&g_B, (double)bb);
            atomicAdd(&g_C, (double)c);
            atomicAdd(&g_count, (unsigned int)n);
        }
    }

    // Last-block finalize: scalar math, output, reset
    if (tid == 0) {
        __threadfence();
        const unsigned int prev = atomicAdd(&g_done, 1u);
        is_last = (prev == (unsigned int)(LOSS_BLOCKS - 1));
    }
    __syncthreads();
    if (is_last && tid == 0) {
        const double A = atomicAdd(&g_A, 0.0);
        const double B = atomicAdd(&g_B, 0.0);
        const double C = atomicAdd(&g_C, 0.0);
        const unsigned int cnt = atomicAdd(&g_count, 0u);

        const double s  = fmin((double)cnt / (double)NPIX, 0.2);
        const double cl = 1.0 - 2.0 * s + s / 6.0;
        const double total = LN2 * (A + s * B + (cl - 1.0) * C);
        out[0] = (float)(-(total / (double)NPIX));

        g_A = 0.0; g_B = 0.0; g_C = 0.0;
        g_count = 0u; g_done = 0u;
    }
}

extern "C" void kernel_launch(void* const* d_in, const int* in_sizes, int n_in,
                              void* d_out, int out_size) {
    const float* x      = (const float*)d_in[0];
    const int*   target = (const int*)d_in[1];
    float*       out    = (float*)d_out;

    dim3 eg(HH / ETH, NB);            // (32, 8) = 256 blocks x 512 threads
    edge_pack_kernel<<<eg, 512>>>(target);

    loss_kernel<<<LOSS_BLOCKS, 128>>>(x, out);
}